// round 16
// baseline (speedup 1.0000x reference)
#include <cuda_runtime.h>
#include <cuda_bf16.h>
#include <cuda_fp16.h>
#include <cstdint>

// Problem constants
#define BB 8
#define TT 2048
#define CC 1024
#define HH 64
#define BT (BB * TT)             // 16384 rows
#define NSPLIT 4
#define SPLIT_LEN (TT / NSPLIT)  // 512
#define NQTILE (TT / 128)        // 16

// q pre-scale: (1/sqrt(64)) * log2(e)  -> softmax in exp2 domain
#define SCALE_LOG2E 0.18033688011112042f

// Scratch (device globals)
__device__ __align__(16) __half g_qh[BT * HH];  // swizzled 128B rows, q pre-scaled
__device__ __align__(16) __half g_kh[BT * HH];  // swizzled 128B rows
__device__ __align__(16) __half g_vh[BT * HH];  // swizzled 128B rows
__device__ float g_pm[NSPLIT * BT];
__device__ float g_pl[NSPLIT * BT];
__device__ float g_po[NSPLIT * BT * HH];
__device__ __align__(16) __nv_bfloat16 g_whi[3 * HH * CC];
__device__ __align__(16) __nv_bfloat16 g_wlo[3 * HH * CC];

// ---------------------------------------------------------------------------
// helpers
// ---------------------------------------------------------------------------
__device__ __forceinline__ uint32_t smem_u32(const void* p) {
    uint32_t a;
    asm("{ .reg .u64 t; cvta.to.shared.u64 t, %1; cvt.u32.u64 %0, t; }"
        : "=r"(a) : "l"(p));
    return a;
}

__device__ __forceinline__ void ldsm4(uint32_t* r, uint32_t addr) {
    asm volatile("ldmatrix.sync.aligned.m8n8.x4.shared.b16 {%0,%1,%2,%3}, [%4];"
                 : "=r"(r[0]), "=r"(r[1]), "=r"(r[2]), "=r"(r[3]) : "r"(addr));
}

__device__ __forceinline__ void ldsm4t(uint32_t* r, uint32_t addr) {
    asm volatile("ldmatrix.sync.aligned.m8n8.x4.trans.shared.b16 {%0,%1,%2,%3}, [%4];"
                 : "=r"(r[0]), "=r"(r[1]), "=r"(r[2]), "=r"(r[3]) : "r"(addr));
}

__device__ __forceinline__ void mma16816(float* c, const uint32_t* a,
                                         uint32_t b0, uint32_t b1) {
    asm volatile(
        "mma.sync.aligned.m16n8k16.row.col.f32.bf16.bf16.f32 "
        "{%0,%1,%2,%3}, {%4,%5,%6,%7}, {%8,%9}, {%0,%1,%2,%3};"
        : "+f"(c[0]), "+f"(c[1]), "+f"(c[2]), "+f"(c[3])
        : "r"(a[0]), "r"(a[1]), "r"(a[2]), "r"(a[3]), "r"(b0), "r"(b1));
}

__device__ __forceinline__ void mma16816h(float* c, const uint32_t* a,
                                          uint32_t b0, uint32_t b1) {
    asm volatile(
        "mma.sync.aligned.m16n8k16.row.col.f32.f16.f16.f32 "
        "{%0,%1,%2,%3}, {%4,%5,%6,%7}, {%8,%9}, {%0,%1,%2,%3};"
        : "+f"(c[0]), "+f"(c[1]), "+f"(c[2]), "+f"(c[3])
        : "r"(a[0]), "r"(a[1]), "r"(a[2]), "r"(a[3]), "r"(b0), "r"(b1));
}

__device__ __forceinline__ uint32_t f2h2(float a, float b) {
    __half2 h = __floats2half2_rn(a, b);
    return *(uint32_t*)&h;
}

__device__ __forceinline__ void cp16(uint32_t dst, const void* src) {
    asm volatile("cp.async.ca.shared.global [%0], [%1], 16;"
                 :: "r"(dst), "l"(src) : "memory");
}
#define CP_COMMIT() asm volatile("cp.async.commit_group;" ::: "memory")
#define CP_WAIT(n)  asm volatile("cp.async.wait_group %0;" :: "n"(n) : "memory")

// ---------------------------------------------------------------------------
// Kernel 0: split W into bf16 hi/lo, transposed to [w][n][k]
// ---------------------------------------------------------------------------
__global__ __launch_bounds__(256) void prep_w_kernel(
    const float* __restrict__ Wk, const float* __restrict__ Wq,
    const float* __restrict__ Wv)
{
    int i = blockIdx.x * 256 + threadIdx.x;
    int w = i >> 16;
    int rem = i & 65535;
    int n = rem >> 10;
    int k = rem & 1023;
    const float* W = (w == 0) ? Wk : (w == 1) ? Wq : Wv;
    float v = W[k * HH + n];
    __nv_bfloat16 h = __float2bfloat16(v);
    float r = v - __bfloat162float(h);
    g_whi[i] = h;
    g_wlo[i] = __float2bfloat16(r);
}

// ---------------------------------------------------------------------------
// Kernel 1: QKV via mma.sync (bf16 split precision).
// A double-buffered (2 x 32KB), B 3-stage cp.async ring (3 x 48KB).
// Outputs fp16, swizzled 128B rows; q pre-scaled by SCALE_LOG2E.
// ---------------------------------------------------------------------------
#define KC2 64
#define NCHUNK2 (CC / KC2)      // 16
#define A_BUF_SZ 32768          // hi 16KB + lo 16KB
#define B_BASE 65536
#define B_STAGE_SZ 49152        // hi 24KB (3w x 8KB) + lo 24KB
#define B_LO_OFF 24576
#define QKV_SMEM (B_BASE + 3 * B_STAGE_SZ)   // 212992 = 208 KB

__global__ __launch_bounds__(256, 1) void qkv_mma_kernel(const float* __restrict__ x)
{
    extern __shared__ __align__(128) char sm[];
    const uint32_t sbase = smem_u32(sm);

    const int tid = threadIdx.x;
    const int wid = tid >> 5;
    const int lane = tid & 31;
    const int m0 = blockIdx.x * 128;

    float acc[3][8][4];
#pragma unroll
    for (int w = 0; w < 3; w++)
#pragma unroll
        for (int nt = 0; nt < 8; nt++)
#pragma unroll
            for (int j = 0; j < 4; j++) acc[w][nt][j] = 0.f;

    float4 xr[8];

    auto issue_b = [&](int c) {
        const int k0 = c * KC2;
        const uint32_t stb = sbase + B_BASE + (uint32_t)((c % 3) * B_STAGE_SZ);
#pragma unroll
        for (int it = 0; it < 6; it++) {
            int g = tid + it * 256;
            int w = g >> 9;
            int n = (g >> 3) & 63;
            int ch = g & 7;
            uint32_t dst = stb + (uint32_t)(w * 8192 + n * 128 + ((ch ^ (n & 7)) * 16));
            const __nv_bfloat16* srch = g_whi + (size_t)w * (HH * CC) + n * CC + k0 + ch * 8;
            const __nv_bfloat16* srcl = g_wlo + (size_t)w * (HH * CC) + n * CC + k0 + ch * 8;
            cp16(dst, srch);
            cp16(dst + B_LO_OFF, srcl);
        }
        CP_COMMIT();
    };

    auto load_a = [&](int k0) {
#pragma unroll
        for (int it = 0; it < 8; it++) {
            int f = tid + it * 256;
            int row = f >> 4, q4 = f & 15;
            xr[it] = *(const float4*)&x[(size_t)(m0 + row) * CC + k0 + q4 * 4];
        }
    };

    load_a(0);
    issue_b(0);
    issue_b(1);

    for (int c = 0; c < NCHUNK2; c++) {
        char* sta = sm + (c & 1) * A_BUF_SZ;
        const uint32_t stba = sbase + (uint32_t)((c & 1) * A_BUF_SZ);
        const uint32_t stbb = sbase + B_BASE + (uint32_t)((c % 3) * B_STAGE_SZ);

        // ---- A regs -> smem (fp32 -> bf16 hi/lo, swizzled) ----
#pragma unroll
        for (int it = 0; it < 8; it++) {
            int f = tid + it * 256;
            int row = f >> 4, q4 = f & 15;
            float4 v = xr[it];
            __nv_bfloat16 h0 = __float2bfloat16(v.x);
            __nv_bfloat16 h1 = __float2bfloat16(v.y);
            __nv_bfloat16 h2 = __float2bfloat16(v.z);
            __nv_bfloat16 h3 = __float2bfloat16(v.w);
            __nv_bfloat16 l0 = __float2bfloat16(v.x - __bfloat162float(h0));
            __nv_bfloat16 l1 = __float2bfloat16(v.y - __bfloat162float(h1));
            __nv_bfloat16 l2 = __float2bfloat16(v.z - __bfloat162float(h2));
            __nv_bfloat16 l3 = __float2bfloat16(v.w - __bfloat162float(h3));
            uint2 hp = make_uint2(
                (uint32_t)__bfloat16_as_ushort(h0) | ((uint32_t)__bfloat16_as_ushort(h1) << 16),
                (uint32_t)__bfloat16_as_ushort(h2) | ((uint32_t)__bfloat16_as_ushort(h3) << 16));
            uint2 lp = make_uint2(
                (uint32_t)__bfloat16_as_ushort(l0) | ((uint32_t)__bfloat16_as_ushort(l1) << 16),
                (uint32_t)__bfloat16_as_ushort(l2) | ((uint32_t)__bfloat16_as_ushort(l3) << 16));
            int ch = q4 >> 1;
            uint32_t off = (uint32_t)(row * 128 + ((ch ^ (row & 7)) * 16) + (q4 & 1) * 8);
            *(uint2*)(sta + off) = hp;
            *(uint2*)(sta + 16384 + off) = lp;
        }

        if (c + 1 < NCHUNK2) {
            load_a((c + 1) * KC2);
            CP_WAIT(1);            // B(c) done (issued 2 iters ago); B(c+1) may pend
        } else {
            CP_WAIT(0);
        }
        __syncthreads();
        // mma(c-1) complete past this sync -> stage (c+2)%3 is free to fill
        if (c + 2 < NCHUNK2) issue_b(c + 2);

        // ---- MMA on A buf c&1, B stage c%3 ----
        const int arow = wid * 16 + (lane & 15);
        const int browbase = (lane & 7) + ((lane >> 4) << 3);
        const int bchlo = (lane >> 3) & 1;
#pragma unroll
        for (int ks = 0; ks < 4; ks++) {
            uint32_t ah[4], al[4];
            {
                int ch = 2 * ks + (lane >> 4);
                uint32_t addr = stba + (uint32_t)(arow * 128 + ((ch ^ (arow & 7)) * 16));
                ldsm4(ah, addr);
                ldsm4(al, addr + 16384);
            }
#pragma unroll
            for (int w = 0; w < 3; w++) {
#pragma unroll
                for (int ng = 0; ng < 4; ng++) {
                    int rowB = ng * 16 + browbase;
                    int ch = bchlo + 2 * ks;
                    uint32_t addr = stbb + (uint32_t)(w * 8192 + rowB * 128 +
                                                      ((ch ^ (rowB & 7)) * 16));
                    uint32_t bh[4], bl[4];
                    ldsm4(bh, addr);
                    ldsm4(bl, addr + B_LO_OFF);
                    mma16816(acc[w][2 * ng],     ah, bh[0], bh[1]);
                    mma16816(acc[w][2 * ng],     ah, bl[0], bl[1]);
                    mma16816(acc[w][2 * ng],     al, bh[0], bh[1]);
                    mma16816(acc[w][2 * ng + 1], ah, bh[2], bh[3]);
                    mma16816(acc[w][2 * ng + 1], ah, bl[2], bl[3]);
                    mma16816(acc[w][2 * ng + 1], al, bh[2], bh[3]);
                }
            }
        }
    }

    char* outs[3] = {(char*)g_kh, (char*)g_qh, (char*)g_vh};
    const float muls[3] = {1.f, SCALE_LOG2E, 1.f};
    const int r0 = m0 + wid * 16 + (lane >> 2);
    const int r1 = r0 + 8;
    const uint32_t inner = (lane & 3) * 4;
#pragma unroll
    for (int w = 0; w < 3; w++) {
        char* op = outs[w];
        float mu = muls[w];
#pragma unroll
        for (int nt = 0; nt < 8; nt++) {
            uint32_t a0 = f2h2(acc[w][nt][0] * mu, acc[w][nt][1] * mu);
            uint32_t a1 = f2h2(acc[w][nt][2] * mu, acc[w][nt][3] * mu);
            *(uint32_t*)(op + (size_t)r0 * 128 + ((nt ^ (r0 & 7)) * 16) + inner) = a0;
            *(uint32_t*)(op + (size_t)r1 * 128 + ((nt ^ (r1 & 7)) * 16) + inner) = a1;
        }
    }
}

// ---------------------------------------------------------------------------
// Kernel 2: FA-2 flash attention, fp16 mma, causal, split-K.
// nact==1 qtiles write final output directly; others write partials.
// (unchanged from passing R15)
// ---------------------------------------------------------------------------
#define ATTN_SMEM (16384 + 2 * 16384)   // 48 KB dynamic

__global__ __launch_bounds__(256, 2) void attn_mma_kernel(float* __restrict__ out)
{
    extern __shared__ __align__(128) char dsm[];

    const int qtile = blockIdx.x;
    const int b = blockIdx.y;
    const int split = blockIdx.z;
    const int tid = threadIdx.x;
    const int wid = tid >> 5;
    const int lane = tid & 31;

    const int qrow0 = qtile * 128;
    const int ks0 = split * SPLIT_LEN;
    if (ks0 >= qrow0 + 128) return;
    const int ks1 = min(ks0 + SPLIT_LEN, qrow0 + 128);
    const int ntile = (ks1 - ks0) >> 6;
    const int nact = (qtile >> 2) + 1;

    const uint32_t sQb = smem_u32(dsm);
    const uint32_t sKVb = sQb + 16384;

    {
        const char* srcQ = (const char*)g_qh + (size_t)(b * TT + qrow0) * 128;
#pragma unroll
        for (int i = 0; i < 4; i++) {
            int f = tid + i * 256;
            cp16(sQb + f * 16, srcQ + f * 16);
        }
        const char* srcK = (const char*)g_kh + (size_t)(b * TT + ks0) * 128;
        const char* srcV = (const char*)g_vh + (size_t)(b * TT + ks0) * 128;
#pragma unroll
        for (int i = 0; i < 2; i++) {
            int f = tid + i * 256;
            cp16(sKVb + f * 16, srcK + f * 16);
            cp16(sKVb + 8192 + f * 16, srcV + f * 16);
        }
        CP_COMMIT();
    }

    float o[8][4];
#pragma unroll
    for (int ng = 0; ng < 8; ng++)
#pragma unroll
        for (int j = 0; j < 4; j++) o[ng][j] = 0.f;
    float m0 = -1e30f, m1 = -1e30f, l0 = 0.f, l1 = 0.f;

    const int t0 = qrow0 + wid * 16 + (lane >> 2);
    const int t1 = t0 + 8;
    const int wmin = qrow0 + wid * 16;
    const int wmax = wmin + 15;

    uint32_t aq[4][4];
    bool qloaded = false;

    const int vkeybase = ((lane >> 3) & 1) * 8 + (lane & 7);
    const int vchsel = lane >> 4;

    for (int it = 0; it < ntile; it++) {
        const int s0 = ks0 + it * 64;
        const uint32_t stg = sKVb + (uint32_t)((it & 1) * 16384);

        CP_WAIT(0);
        __syncthreads();

        if (it + 1 < ntile) {
            const int sn = s0 + 64;
            const char* srcK = (const char*)g_kh + (size_t)(b * TT + sn) * 128;
            const char* srcV = (const char*)g_vh + (size_t)(b * TT + sn) * 128;
            uint32_t dst = sKVb + (uint32_t)(((it + 1) & 1) * 16384);
#pragma unroll
            for (int i = 0; i < 2; i++) {
                int f = tid + i * 256;
                cp16(dst + f * 16, srcK + f * 16);
                cp16(dst + 8192 + f * 16, srcV + f * 16);
            }
            CP_COMMIT();
        }

        if (!qloaded) {
            int row = wid * 16 + (lane & 15);
#pragma unroll
            for (int ks = 0; ks < 4; ks++) {
                int chunk = 2 * ks + (lane >> 4);
                ldsm4(aq[ks], sQb + (uint32_t)(row * 128 + ((chunk ^ (row & 7)) * 16)));
            }
            qloaded = true;
        }

        if (s0 > wmax) continue;

        float s[8][4];
#pragma unroll
        for (int ng = 0; ng < 8; ng++)
#pragma unroll
            for (int j = 0; j < 4; j++) s[ng][j] = 0.f;

#pragma unroll
        for (int kg = 0; kg < 4; kg++) {
            int rowB = kg * 16 + (lane & 7) + ((lane >> 4) << 3);
#pragma unroll
            for (int ks = 0; ks < 4; ks++) {
                int chunk = ((lane >> 3) & 1) + 2 * ks;
                uint32_t addr = stg + (uint32_t)(rowB * 128 + ((chunk ^ (rowB & 7)) * 16));
                uint32_t bk[4];
                ldsm4(bk, addr);
                mma16816h(s[2 * kg],     aq[ks], bk[0], bk[1]);
                mma16816h(s[2 * kg + 1], aq[ks], bk[2], bk[3]);
            }
        }

        if (s0 + 63 >= wmin) {
#pragma unroll
            for (int ng = 0; ng < 8; ng++) {
                int scol = s0 + ng * 8 + (lane & 3) * 2;
                if (scol     > t0) s[ng][0] = -1e30f;
                if (scol + 1 > t0) s[ng][1] = -1e30f;
                if (scol     > t1) s[ng][2] = -1e30f;
                if (scol + 1 > t1) s[ng][3] = -1e30f;
            }
        }

        float mx0 = -1e30f, mx1 = -1e30f;
#pragma unroll
        for (int ng = 0; ng < 8; ng++) {
            mx0 = fmaxf(mx0, fmaxf(s[ng][0], s[ng][1]));
            mx1 = fmaxf(mx1, fmaxf(s[ng][2], s[ng][3]));
        }
        mx0 = fmaxf(mx0, __shfl_xor_sync(0xffffffffu, mx0, 1));
        mx0 = fmaxf(mx0, __shfl_xor_sync(0xffffffffu, mx0, 2));
        mx1 = fmaxf(mx1, __shfl_xor_sync(0xffffffffu, mx1, 1));
        mx1 = fmaxf(mx1, __shfl_xor_sync(0xffffffffu, mx1, 2));

        float mn0 = fmaxf(m0, mx0);
        float mn1 = fmaxf(m1, mx1);
        float c0 = exp2f(m0 - mn0);
        float c1 = exp2f(m1 - mn1);

        float sum0 = 0.f, sum1 = 0.f;
#pragma unroll
        for (int ng = 0; ng < 8; ng++) {
            s[ng][0] = exp2f(s[ng][0] - mn0);
            s[ng][1] = exp2f(s[ng][1] - mn0);
            s[ng][2] = exp2f(s[ng][2] - mn1);
            s[ng][3] = exp2f(s[ng][3] - mn1);
            sum0 += s[ng][0] + s[ng][1];
            sum1 += s[ng][2] + s[ng][3];
        }
        sum0 += __shfl_xor_sync(0xffffffffu, sum0, 1);
        sum0 += __shfl_xor_sync(0xffffffffu, sum0, 2);
        sum1 += __shfl_xor_sync(0xffffffffu, sum1, 1);
        sum1 += __shfl_xor_sync(0xffffffffu, sum1, 2);

        l0 = l0 * c0 + sum0;
        l1 = l1 * c1 + sum1;
        m0 = mn0; m1 = mn1;

#pragma unroll
        for (int ng = 0; ng < 8; ng++) {
            o[ng][0] *= c0; o[ng][1] *= c0;
            o[ng][2] *= c1; o[ng][3] *= c1;
        }

        const uint32_t sVstg = stg + 8192;
#pragma unroll
        for (int ks = 0; ks < 4; ks++) {
            uint32_t ap[4];
            ap[0] = f2h2(s[2 * ks][0],     s[2 * ks][1]);
            ap[1] = f2h2(s[2 * ks][2],     s[2 * ks][3]);
            ap[2] = f2h2(s[2 * ks + 1][0], s[2 * ks + 1][1]);
            ap[3] = f2h2(s[2 * ks + 1][2], s[2 * ks + 1][3]);
            int keyl = ks * 16 + vkeybase;
#pragma unroll
            for (int hg = 0; hg < 4; hg++) {
                int ch = hg * 2 + vchsel;
                uint32_t addr = sVstg + (uint32_t)(keyl * 128 + ((ch ^ (keyl & 7)) * 16));
                uint32_t bv[4];
                ldsm4t(bv, addr);
                mma16816h(o[2 * hg],     ap, bv[0], bv[1]);
                mma16816h(o[2 * hg + 1], ap, bv[2], bv[3]);
            }
        }
    }

    const int grow0 = b * TT + t0;
    const int grow1 = b * TT + t1;

    if (nact == 1) {
        float inv0 = 1.f / l0;
        float inv1 = 1.f / l1;
        float* oo0 = out + (size_t)grow0 * HH;
        float* oo1 = out + (size_t)grow1 * HH;
#pragma unroll
        for (int ng = 0; ng < 8; ng++) {
            int col = ng * 8 + (lane & 3) * 2;
            *(float2*)&oo0[col] = make_float2(o[ng][0] * inv0, o[ng][1] * inv0);
            *(float2*)&oo1[col] = make_float2(o[ng][2] * inv1, o[ng][3] * inv1);
        }
        return;
    }

    if ((lane & 3) == 0) {
        g_pm[split * BT + grow0] = m0;
        g_pl[split * BT + grow0] = l0;
        g_pm[split * BT + grow1] = m1;
        g_pl[split * BT + grow1] = l1;
    }
    float* po0 = g_po + ((size_t)split * BT + grow0) * HH;
    float* po1 = g_po + ((size_t)split * BT + grow1) * HH;
#pragma unroll
    for (int ng = 0; ng < 8; ng++) {
        int col = ng * 8 + (lane & 3) * 2;
        *(float2*)&po0[col] = make_float2(o[ng][0], o[ng][1]);
        *(float2*)&po1[col] = make_float2(o[ng][2], o[ng][3]);
    }
}

// ---------------------------------------------------------------------------
// Kernel 3: combine partials. 256 threads; 16 rows/block, 16 threads x float4
// per row. Unrolled NSPLIT loops with i<nact predicates; nact==1 rows were
// written directly by attn -> early exit.
// ---------------------------------------------------------------------------
__global__ __launch_bounds__(256) void combine_kernel(float* __restrict__ out)
{
    const int row = blockIdx.x * 16 + (threadIdx.x >> 4);
    const int h = (threadIdx.x & 15) * 4;
    const int t = row & (TT - 1);
    const int nact = (t >> 9) + 1;
    if (nact == 1) return;

    float mv[NSPLIT], lv[NSPLIT], wgt[NSPLIT];
    float M = -1e30f;
#pragma unroll
    for (int i = 0; i < NSPLIT; i++) {
        if (i < nact) {
            mv[i] = g_pm[i * BT + row];
            lv[i] = g_pl[i * BT + row];
            M = fmaxf(M, mv[i]);
        }
    }
    float L = 0.f;
#pragma unroll
    for (int i = 0; i < NSPLIT; i++) {
        if (i < nact) {
            wgt[i] = exp2f(mv[i] - M);
            L += lv[i] * wgt[i];
        }
    }
    float4 acc = make_float4(0.f, 0.f, 0.f, 0.f);
#pragma unroll
    for (int i = 0; i < NSPLIT; i++) {
        if (i < nact) {
            float4 p = *(const float4*)&g_po[((size_t)i * BT + row) * HH + h];
            acc.x += p.x * wgt[i];
            acc.y += p.y * wgt[i];
            acc.z += p.z * wgt[i];
            acc.w += p.w * wgt[i];
        }
    }
    float inv = 1.f / L;
    *(float4*)&out[(size_t)row * HH + h] =
        make_float4(acc.x * inv, acc.y * inv, acc.z * inv, acc.w * inv);
}

// ---------------------------------------------------------------------------
extern "C" void kernel_launch(void* const* d_in, const int* in_sizes, int n_in,
                              void* d_out, int out_size)
{
    const float* x  = (const float*)d_in[0];
    const float* Wk = (const float*)d_in[1];
    const float* Wq = (const float*)d_in[2];
    const float* Wv = (const float*)d_in[3];
    float* out = (float*)d_out;

    static bool attr_set = false;
    if (!attr_set) {
        cudaFuncSetAttribute(qkv_mma_kernel,
                             cudaFuncAttributeMaxDynamicSharedMemorySize, QKV_SMEM);
        cudaFuncSetAttribute(attn_mma_kernel,
                             cudaFuncAttributeMaxDynamicSharedMemorySize, ATTN_SMEM);
        attr_set = true;
    }

    prep_w_kernel<<<3 * HH * CC / 256, 256>>>(Wk, Wq, Wv);
    qkv_mma_kernel<<<BT / 128, 256, QKV_SMEM>>>(x);
    attn_mma_kernel<<<dim3(NQTILE, BB, NSPLIT), 256, ATTN_SMEM>>>(out);
    combine_kernel<<<dim3(BT / 16), 256>>>(out);
}

// round 17
// speedup vs baseline: 1.0415x; 1.0415x over previous
#include <cuda_runtime.h>
#include <cuda_bf16.h>
#include <cuda_fp16.h>
#include <cstdint>

// Problem constants
#define BB 8
#define TT 2048
#define CC 1024
#define HH 64
#define BT (BB * TT)             // 16384 rows
#define NSPLIT 4
#define SPLIT_LEN (TT / NSPLIT)  // 512
#define NQTILE (TT / 128)        // 16

// q pre-scale: (1/sqrt(64)) * log2(e)  -> softmax in exp2 domain
#define SCALE_LOG2E 0.18033688011112042f

// Scratch (device globals)
__device__ __align__(16) __half g_qh[BT * HH];  // swizzled 128B rows, q pre-scaled
__device__ __align__(16) __half g_kh[BT * HH];  // swizzled 128B rows
__device__ __align__(16) __half g_vh[BT * HH];  // swizzled 128B rows
__device__ float g_pm[NSPLIT * BT];
__device__ float g_pl[NSPLIT * BT];
__device__ float g_po[NSPLIT * BT * HH];
__device__ __align__(16) __nv_bfloat16 g_whi[3 * HH * CC];
__device__ __align__(16) __nv_bfloat16 g_wlo[3 * HH * CC];

// ---------------------------------------------------------------------------
// helpers
// ---------------------------------------------------------------------------
__device__ __forceinline__ uint32_t smem_u32(const void* p) {
    uint32_t a;
    asm("{ .reg .u64 t; cvta.to.shared.u64 t, %1; cvt.u32.u64 %0, t; }"
        : "=r"(a) : "l"(p));
    return a;
}

__device__ __forceinline__ void ldsm4(uint32_t* r, uint32_t addr) {
    asm volatile("ldmatrix.sync.aligned.m8n8.x4.shared.b16 {%0,%1,%2,%3}, [%4];"
                 : "=r"(r[0]), "=r"(r[1]), "=r"(r[2]), "=r"(r[3]) : "r"(addr));
}

__device__ __forceinline__ void ldsm4t(uint32_t* r, uint32_t addr) {
    asm volatile("ldmatrix.sync.aligned.m8n8.x4.trans.shared.b16 {%0,%1,%2,%3}, [%4];"
                 : "=r"(r[0]), "=r"(r[1]), "=r"(r[2]), "=r"(r[3]) : "r"(addr));
}

__device__ __forceinline__ void mma16816(float* c, const uint32_t* a,
                                         uint32_t b0, uint32_t b1) {
    asm volatile(
        "mma.sync.aligned.m16n8k16.row.col.f32.bf16.bf16.f32 "
        "{%0,%1,%2,%3}, {%4,%5,%6,%7}, {%8,%9}, {%0,%1,%2,%3};"
        : "+f"(c[0]), "+f"(c[1]), "+f"(c[2]), "+f"(c[3])
        : "r"(a[0]), "r"(a[1]), "r"(a[2]), "r"(a[3]), "r"(b0), "r"(b1));
}

__device__ __forceinline__ void mma16816h(float* c, const uint32_t* a,
                                          uint32_t b0, uint32_t b1) {
    asm volatile(
        "mma.sync.aligned.m16n8k16.row.col.f32.f16.f16.f32 "
        "{%0,%1,%2,%3}, {%4,%5,%6,%7}, {%8,%9}, {%0,%1,%2,%3};"
        : "+f"(c[0]), "+f"(c[1]), "+f"(c[2]), "+f"(c[3])
        : "r"(a[0]), "r"(a[1]), "r"(a[2]), "r"(a[3]), "r"(b0), "r"(b1));
}

__device__ __forceinline__ uint32_t f2h2(float a, float b) {
    __half2 h = __floats2half2_rn(a, b);
    return *(uint32_t*)&h;
}

__device__ __forceinline__ void cp16(uint32_t dst, const void* src) {
    asm volatile("cp.async.ca.shared.global [%0], [%1], 16;"
                 :: "r"(dst), "l"(src) : "memory");
}
#define CP_COMMIT() asm volatile("cp.async.commit_group;" ::: "memory")
#define CP_WAIT(n)  asm volatile("cp.async.wait_group %0;" :: "n"(n) : "memory")

// ---------------------------------------------------------------------------
// Kernel 0: split W into bf16 hi/lo, transposed to [w][n][k]
// ---------------------------------------------------------------------------
__global__ __launch_bounds__(256) void prep_w_kernel(
    const float* __restrict__ Wk, const float* __restrict__ Wq,
    const float* __restrict__ Wv)
{
    int i = blockIdx.x * 256 + threadIdx.x;
    int w = i >> 16;
    int rem = i & 65535;
    int n = rem >> 10;
    int k = rem & 1023;
    const float* W = (w == 0) ? Wk : (w == 1) ? Wq : Wv;
    float v = W[k * HH + n];
    __nv_bfloat16 h = __float2bfloat16(v);
    float r = v - __bfloat162float(h);
    g_whi[i] = h;
    g_wlo[i] = __float2bfloat16(r);
}

// ---------------------------------------------------------------------------
// Kernel 1: QKV via mma.sync (bf16 split precision). Single-barrier pipeline,
// 2-stage buffers (reverted from R16's 3-stage ring, which regressed).
// Outputs fp16, swizzled 128B rows; q pre-scaled by SCALE_LOG2E.
// ---------------------------------------------------------------------------
#define KC2 64
#define NCHUNK2 (CC / KC2)      // 16
#define QA_HI 0
#define QA_LO 16384
#define QB_HI 32768             // + w*8192
#define QB_LO 57344             // + w*8192
#define QSTAGE 81920
#define QKV_SMEM (2 * QSTAGE)   // 160 KB

__global__ __launch_bounds__(256, 1) void qkv_mma_kernel(const float* __restrict__ x)
{
    extern __shared__ __align__(128) char sm[];
    const uint32_t sbase = smem_u32(sm);

    const int tid = threadIdx.x;
    const int wid = tid >> 5;
    const int lane = tid & 31;
    const int m0 = blockIdx.x * 128;

    float acc[3][8][4];
#pragma unroll
    for (int w = 0; w < 3; w++)
#pragma unroll
        for (int nt = 0; nt < 8; nt++)
#pragma unroll
            for (int j = 0; j < 4; j++) acc[w][nt][j] = 0.f;

    float4 xr[8];

    auto issue_b = [&](int k0, uint32_t stb) {
#pragma unroll
        for (int it = 0; it < 6; it++) {
            int g = tid + it * 256;
            int w = g >> 9;
            int n = (g >> 3) & 63;
            int ch = g & 7;
            uint32_t dst = stb + (uint32_t)(w * 8192 + n * 128 + ((ch ^ (n & 7)) * 16));
            const __nv_bfloat16* srch = g_whi + (size_t)w * (HH * CC) + n * CC + k0 + ch * 8;
            const __nv_bfloat16* srcl = g_wlo + (size_t)w * (HH * CC) + n * CC + k0 + ch * 8;
            cp16(QB_HI + dst, srch);
            cp16(QB_LO + dst, srcl);
        }
        CP_COMMIT();
    };

    auto load_a = [&](int k0) {
#pragma unroll
        for (int it = 0; it < 8; it++) {
            int f = tid + it * 256;
            int row = f >> 4, q4 = f & 15;
            xr[it] = *(const float4*)&x[(size_t)(m0 + row) * CC + k0 + q4 * 4];
        }
    };

    load_a(0);
    issue_b(0, sbase);

    for (int c = 0; c < NCHUNK2; c++) {
        const int buf = c & 1;
        char* st = sm + buf * QSTAGE;
        const uint32_t stb = sbase + buf * QSTAGE;

#pragma unroll
        for (int it = 0; it < 8; it++) {
            int f = tid + it * 256;
            int row = f >> 4, q4 = f & 15;
            float4 v = xr[it];
            __nv_bfloat16 h0 = __float2bfloat16(v.x);
            __nv_bfloat16 h1 = __float2bfloat16(v.y);
            __nv_bfloat16 h2 = __float2bfloat16(v.z);
            __nv_bfloat16 h3 = __float2bfloat16(v.w);
            __nv_bfloat16 l0 = __float2bfloat16(v.x - __bfloat162float(h0));
            __nv_bfloat16 l1 = __float2bfloat16(v.y - __bfloat162float(h1));
            __nv_bfloat16 l2 = __float2bfloat16(v.z - __bfloat162float(h2));
            __nv_bfloat16 l3 = __float2bfloat16(v.w - __bfloat162float(h3));
            uint2 hp = make_uint2(
                (uint32_t)__bfloat16_as_ushort(h0) | ((uint32_t)__bfloat16_as_ushort(h1) << 16),
                (uint32_t)__bfloat16_as_ushort(h2) | ((uint32_t)__bfloat16_as_ushort(h3) << 16));
            uint2 lp = make_uint2(
                (uint32_t)__bfloat16_as_ushort(l0) | ((uint32_t)__bfloat16_as_ushort(l1) << 16),
                (uint32_t)__bfloat16_as_ushort(l2) | ((uint32_t)__bfloat16_as_ushort(l3) << 16));
            int ch = q4 >> 1;
            uint32_t off = (uint32_t)(row * 128 + ((ch ^ (row & 7)) * 16) + (q4 & 1) * 8);
            *(uint2*)(st + QA_HI + off) = hp;
            *(uint2*)(st + QA_LO + off) = lp;
        }

        if (c + 1 < NCHUNK2) load_a((c + 1) * KC2);
        CP_WAIT(0);
        __syncthreads();
        if (c + 1 < NCHUNK2) issue_b((c + 1) * KC2, sbase + ((c + 1) & 1) * QSTAGE);

        const int arow = wid * 16 + (lane & 15);
        const int browbase = (lane & 7) + ((lane >> 4) << 3);
        const int bchlo = (lane >> 3) & 1;
#pragma unroll
        for (int ks = 0; ks < 4; ks++) {
            uint32_t ah[4], al[4];
            {
                int ch = 2 * ks + (lane >> 4);
                uint32_t addr = stb + (uint32_t)(arow * 128 + ((ch ^ (arow & 7)) * 16));
                ldsm4(ah, QA_HI + addr);
                ldsm4(al, QA_LO + addr);
            }
#pragma unroll
            for (int w = 0; w < 3; w++) {
#pragma unroll
                for (int ng = 0; ng < 4; ng++) {
                    int rowB = ng * 16 + browbase;
                    int ch = bchlo + 2 * ks;
                    uint32_t addr = stb + (uint32_t)(w * 8192 + rowB * 128 +
                                                     ((ch ^ (rowB & 7)) * 16));
                    uint32_t bh[4], bl[4];
                    ldsm4(bh, QB_HI + addr);
                    ldsm4(bl, QB_LO + addr);
                    mma16816(acc[w][2 * ng],     ah, bh[0], bh[1]);
                    mma16816(acc[w][2 * ng],     ah, bl[0], bl[1]);
                    mma16816(acc[w][2 * ng],     al, bh[0], bh[1]);
                    mma16816(acc[w][2 * ng + 1], ah, bh[2], bh[3]);
                    mma16816(acc[w][2 * ng + 1], ah, bl[2], bl[3]);
                    mma16816(acc[w][2 * ng + 1], al, bh[2], bh[3]);
                }
            }
        }
    }

    char* outs[3] = {(char*)g_kh, (char*)g_qh, (char*)g_vh};
    const float muls[3] = {1.f, SCALE_LOG2E, 1.f};
    const int r0 = m0 + wid * 16 + (lane >> 2);
    const int r1 = r0 + 8;
    const uint32_t inner = (lane & 3) * 4;
#pragma unroll
    for (int w = 0; w < 3; w++) {
        char* op = outs[w];
        float mu = muls[w];
#pragma unroll
        for (int nt = 0; nt < 8; nt++) {
            uint32_t a0 = f2h2(acc[w][nt][0] * mu, acc[w][nt][1] * mu);
            uint32_t a1 = f2h2(acc[w][nt][2] * mu, acc[w][nt][3] * mu);
            *(uint32_t*)(op + (size_t)r0 * 128 + ((nt ^ (r0 & 7)) * 16) + inner) = a0;
            *(uint32_t*)(op + (size_t)r1 * 128 + ((nt ^ (r1 & 7)) * 16) + inner) = a1;
        }
    }
}

// ---------------------------------------------------------------------------
// Kernel 2: FA-2 flash attention, fp16 mma, causal, split-K.
// nact==1 qtiles write final output directly; others write partials.
// (unchanged from passing R15)
// ---------------------------------------------------------------------------
#define ATTN_SMEM (16384 + 2 * 16384)   // 48 KB dynamic

__global__ __launch_bounds__(256, 2) void attn_mma_kernel(float* __restrict__ out)
{
    extern __shared__ __align__(128) char dsm[];

    const int qtile = blockIdx.x;
    const int b = blockIdx.y;
    const int split = blockIdx.z;
    const int tid = threadIdx.x;
    const int wid = tid >> 5;
    const int lane = tid & 31;

    const int qrow0 = qtile * 128;
    const int ks0 = split * SPLIT_LEN;
    if (ks0 >= qrow0 + 128) return;
    const int ks1 = min(ks0 + SPLIT_LEN, qrow0 + 128);
    const int ntile = (ks1 - ks0) >> 6;
    const int nact = (qtile >> 2) + 1;

    const uint32_t sQb = smem_u32(dsm);
    const uint32_t sKVb = sQb + 16384;

    {
        const char* srcQ = (const char*)g_qh + (size_t)(b * TT + qrow0) * 128;
#pragma unroll
        for (int i = 0; i < 4; i++) {
            int f = tid + i * 256;
            cp16(sQb + f * 16, srcQ + f * 16);
        }
        const char* srcK = (const char*)g_kh + (size_t)(b * TT + ks0) * 128;
        const char* srcV = (const char*)g_vh + (size_t)(b * TT + ks0) * 128;
#pragma unroll
        for (int i = 0; i < 2; i++) {
            int f = tid + i * 256;
            cp16(sKVb + f * 16, srcK + f * 16);
            cp16(sKVb + 8192 + f * 16, srcV + f * 16);
        }
        CP_COMMIT();
    }

    float o[8][4];
#pragma unroll
    for (int ng = 0; ng < 8; ng++)
#pragma unroll
        for (int j = 0; j < 4; j++) o[ng][j] = 0.f;
    float m0 = -1e30f, m1 = -1e30f, l0 = 0.f, l1 = 0.f;

    const int t0 = qrow0 + wid * 16 + (lane >> 2);
    const int t1 = t0 + 8;
    const int wmin = qrow0 + wid * 16;
    const int wmax = wmin + 15;

    uint32_t aq[4][4];
    bool qloaded = false;

    const int vkeybase = ((lane >> 3) & 1) * 8 + (lane & 7);
    const int vchsel = lane >> 4;

    for (int it = 0; it < ntile; it++) {
        const int s0 = ks0 + it * 64;
        const uint32_t stg = sKVb + (uint32_t)((it & 1) * 16384);

        CP_WAIT(0);
        __syncthreads();

        if (it + 1 < ntile) {
            const int sn = s0 + 64;
            const char* srcK = (const char*)g_kh + (size_t)(b * TT + sn) * 128;
            const char* srcV = (const char*)g_vh + (size_t)(b * TT + sn) * 128;
            uint32_t dst = sKVb + (uint32_t)(((it + 1) & 1) * 16384);
#pragma unroll
            for (int i = 0; i < 2; i++) {
                int f = tid + i * 256;
                cp16(dst + f * 16, srcK + f * 16);
                cp16(dst + 8192 + f * 16, srcV + f * 16);
            }
            CP_COMMIT();
        }

        if (!qloaded) {
            int row = wid * 16 + (lane & 15);
#pragma unroll
            for (int ks = 0; ks < 4; ks++) {
                int chunk = 2 * ks + (lane >> 4);
                ldsm4(aq[ks], sQb + (uint32_t)(row * 128 + ((chunk ^ (row & 7)) * 16)));
            }
            qloaded = true;
        }

        if (s0 > wmax) continue;

        float s[8][4];
#pragma unroll
        for (int ng = 0; ng < 8; ng++)
#pragma unroll
            for (int j = 0; j < 4; j++) s[ng][j] = 0.f;

#pragma unroll
        for (int kg = 0; kg < 4; kg++) {
            int rowB = kg * 16 + (lane & 7) + ((lane >> 4) << 3);
#pragma unroll
            for (int ks = 0; ks < 4; ks++) {
                int chunk = ((lane >> 3) & 1) + 2 * ks;
                uint32_t addr = stg + (uint32_t)(rowB * 128 + ((chunk ^ (rowB & 7)) * 16));
                uint32_t bk[4];
                ldsm4(bk, addr);
                mma16816h(s[2 * kg],     aq[ks], bk[0], bk[1]);
                mma16816h(s[2 * kg + 1], aq[ks], bk[2], bk[3]);
            }
        }

        if (s0 + 63 >= wmin) {
#pragma unroll
            for (int ng = 0; ng < 8; ng++) {
                int scol = s0 + ng * 8 + (lane & 3) * 2;
                if (scol     > t0) s[ng][0] = -1e30f;
                if (scol + 1 > t0) s[ng][1] = -1e30f;
                if (scol     > t1) s[ng][2] = -1e30f;
                if (scol + 1 > t1) s[ng][3] = -1e30f;
            }
        }

        float mx0 = -1e30f, mx1 = -1e30f;
#pragma unroll
        for (int ng = 0; ng < 8; ng++) {
            mx0 = fmaxf(mx0, fmaxf(s[ng][0], s[ng][1]));
            mx1 = fmaxf(mx1, fmaxf(s[ng][2], s[ng][3]));
        }
        mx0 = fmaxf(mx0, __shfl_xor_sync(0xffffffffu, mx0, 1));
        mx0 = fmaxf(mx0, __shfl_xor_sync(0xffffffffu, mx0, 2));
        mx1 = fmaxf(mx1, __shfl_xor_sync(0xffffffffu, mx1, 1));
        mx1 = fmaxf(mx1, __shfl_xor_sync(0xffffffffu, mx1, 2));

        float mn0 = fmaxf(m0, mx0);
        float mn1 = fmaxf(m1, mx1);
        float c0 = exp2f(m0 - mn0);
        float c1 = exp2f(m1 - mn1);

        float sum0 = 0.f, sum1 = 0.f;
#pragma unroll
        for (int ng = 0; ng < 8; ng++) {
            s[ng][0] = exp2f(s[ng][0] - mn0);
            s[ng][1] = exp2f(s[ng][1] - mn0);
            s[ng][2] = exp2f(s[ng][2] - mn1);
            s[ng][3] = exp2f(s[ng][3] - mn1);
            sum0 += s[ng][0] + s[ng][1];
            sum1 += s[ng][2] + s[ng][3];
        }
        sum0 += __shfl_xor_sync(0xffffffffu, sum0, 1);
        sum0 += __shfl_xor_sync(0xffffffffu, sum0, 2);
        sum1 += __shfl_xor_sync(0xffffffffu, sum1, 1);
        sum1 += __shfl_xor_sync(0xffffffffu, sum1, 2);

        l0 = l0 * c0 + sum0;
        l1 = l1 * c1 + sum1;
        m0 = mn0; m1 = mn1;

#pragma unroll
        for (int ng = 0; ng < 8; ng++) {
            o[ng][0] *= c0; o[ng][1] *= c0;
            o[ng][2] *= c1; o[ng][3] *= c1;
        }

        const uint32_t sVstg = stg + 8192;
#pragma unroll
        for (int ks = 0; ks < 4; ks++) {
            uint32_t ap[4];
            ap[0] = f2h2(s[2 * ks][0],     s[2 * ks][1]);
            ap[1] = f2h2(s[2 * ks][2],     s[2 * ks][3]);
            ap[2] = f2h2(s[2 * ks + 1][0], s[2 * ks + 1][1]);
            ap[3] = f2h2(s[2 * ks + 1][2], s[2 * ks + 1][3]);
            int keyl = ks * 16 + vkeybase;
#pragma unroll
            for (int hg = 0; hg < 4; hg++) {
                int ch = hg * 2 + vchsel;
                uint32_t addr = sVstg + (uint32_t)(keyl * 128 + ((ch ^ (keyl & 7)) * 16));
                uint32_t bv[4];
                ldsm4t(bv, addr);
                mma16816h(o[2 * hg],     ap, bv[0], bv[1]);
                mma16816h(o[2 * hg + 1], ap, bv[2], bv[3]);
            }
        }
    }

    const int grow0 = b * TT + t0;
    const int grow1 = b * TT + t1;

    if (nact == 1) {
        float inv0 = 1.f / l0;
        float inv1 = 1.f / l1;
        float* oo0 = out + (size_t)grow0 * HH;
        float* oo1 = out + (size_t)grow1 * HH;
#pragma unroll
        for (int ng = 0; ng < 8; ng++) {
            int col = ng * 8 + (lane & 3) * 2;
            *(float2*)&oo0[col] = make_float2(o[ng][0] * inv0, o[ng][1] * inv0);
            *(float2*)&oo1[col] = make_float2(o[ng][2] * inv1, o[ng][3] * inv1);
        }
        return;
    }

    if ((lane & 3) == 0) {
        g_pm[split * BT + grow0] = m0;
        g_pl[split * BT + grow0] = l0;
        g_pm[split * BT + grow1] = m1;
        g_pl[split * BT + grow1] = l1;
    }
    float* po0 = g_po + ((size_t)split * BT + grow0) * HH;
    float* po1 = g_po + ((size_t)split * BT + grow1) * HH;
#pragma unroll
    for (int ng = 0; ng < 8; ng++) {
        int col = ng * 8 + (lane & 3) * 2;
        *(float2*)&po0[col] = make_float2(o[ng][0], o[ng][1]);
        *(float2*)&po1[col] = make_float2(o[ng][2], o[ng][3]);
    }
}

// ---------------------------------------------------------------------------
// Kernel 3: combine partials. 256 threads; 16 rows/block, 16 threads x float4
// per row (R16's vectorized version: measured 6.4us).
// ---------------------------------------------------------------------------
__global__ __launch_bounds__(256) void combine_kernel(float* __restrict__ out)
{
    const int row = blockIdx.x * 16 + (threadIdx.x >> 4);
    const int h = (threadIdx.x & 15) * 4;
    const int t = row & (TT - 1);
    const int nact = (t >> 9) + 1;
    if (nact == 1) return;

    float mv[NSPLIT], lv[NSPLIT], wgt[NSPLIT];
    float M = -1e30f;
#pragma unroll
    for (int i = 0; i < NSPLIT; i++) {
        if (i < nact) {
            mv[i] = g_pm[i * BT + row];
            lv[i] = g_pl[i * BT + row];
            M = fmaxf(M, mv[i]);
        }
    }
    float L = 0.f;
#pragma unroll
    for (int i = 0; i < NSPLIT; i++) {
        if (i < nact) {
            wgt[i] = exp2f(mv[i] - M);
            L += lv[i] * wgt[i];
        }
    }
    float4 acc = make_float4(0.f, 0.f, 0.f, 0.f);
#pragma unroll
    for (int i = 0; i < NSPLIT; i++) {
        if (i < nact) {
            float4 p = *(const float4*)&g_po[((size_t)i * BT + row) * HH + h];
            acc.x += p.x * wgt[i];
            acc.y += p.y * wgt[i];
            acc.z += p.z * wgt[i];
            acc.w += p.w * wgt[i];
        }
    }
    float inv = 1.f / L;
    *(float4*)&out[(size_t)row * HH + h] =
        make_float4(acc.x * inv, acc.y * inv, acc.z * inv, acc.w * inv);
}

// ---------------------------------------------------------------------------
extern "C" void kernel_launch(void* const* d_in, const int* in_sizes, int n_in,
                              void* d_out, int out_size)
{
    const float* x  = (const float*)d_in[0];
    const float* Wk = (const float*)d_in[1];
    const float* Wq = (const float*)d_in[2];
    const float* Wv = (const float*)d_in[3];
    float* out = (float*)d_out;

    static bool attr_set = false;
    if (!attr_set) {
        cudaFuncSetAttribute(qkv_mma_kernel,
                             cudaFuncAttributeMaxDynamicSharedMemorySize, QKV_SMEM);
        cudaFuncSetAttribute(attn_mma_kernel,
                             cudaFuncAttributeMaxDynamicSharedMemorySize, ATTN_SMEM);
        attr_set = true;
    }

    prep_w_kernel<<<3 * HH * CC / 256, 256>>>(Wk, Wq, Wv);
    qkv_mma_kernel<<<BT / 128, 256, QKV_SMEM>>>(x);
    attn_mma_kernel<<<dim3(NQTILE, BB, NSPLIT), 256, ATTN_SMEM>>>(out);
    combine_kernel<<<dim3(BT / 16), 256>>>(out);
}